// round 3
// baseline (speedup 1.0000x reference)
#include <cuda_runtime.h>
#include <cuda_bf16.h>

// PositionalEncoding2D:
//   pe[i, b, 2p]   = sin(x[i,b,0] * dt[p])
//   pe[i, b, 2p+1] = cos(x[i,b,1] * dt[p])
//   dt[p] = exp(p * -ln(1e4)/256)
//
// Input : x  [65536 rows][2] fp32;  Output: [65536 rows][512] fp32 = 128 MB.
// Pure store-bandwidth problem. One warp handles TWO rows; each lane produces
// 8 float4 quads (4 per row) -> 8 independent STG.128 in flight (MLP=8).
// Coord load for both rows is one uniform float4. Streaming stores (__stcs):
// output is never re-read and exceeds L2 capacity.

#define NUM_ROWS (2048 * 32)   // 65536

__global__ __launch_bounds__(256)
void pe2d_kernel(const float4* __restrict__ x, float4* __restrict__ out) {
    const int warp = (blockIdx.x * 256 + threadIdx.x) >> 5;  // row-pair index
    const int lane = threadIdx.x & 31;

    // Coords for rows 2w and 2w+1: 4 contiguous floats (uniform in warp)
    const float4 xy2 = __ldg(x + warp);
    // row0: (xy2.x, xy2.y)   row1: (xy2.z, xy2.w)

    // dt for quad t: exp(2t * C), C = -ln(1e4)/256
    const float twoC = -9.210340371976184f / 128.0f;
    const float r    = 0.9646616199111993f;            // pair step 1e4^(-1/256)
    const float d0 = __expf((float)lane * twoC);       // quad lane
    const float d1 = d0 * 0.1f;                        // quad lane+32 (step = 1e4^(-1/4))
    const float d2 = d1 * 0.1f;
    const float d3 = d2 * 0.1f;
    const float e0 = d0 * r, e1 = d1 * r, e2 = d2 * r, e3 = d3 * r;

    float4* o = out + (size_t)warp * 256 + lane;

    float4 a0, a1, a2, a3, b0, b1, b2, b3;
    // row 0
    a0.x = __sinf(xy2.x * d0); a0.y = __cosf(xy2.y * d0);
    a0.z = __sinf(xy2.x * e0); a0.w = __cosf(xy2.y * e0);
    a1.x = __sinf(xy2.x * d1); a1.y = __cosf(xy2.y * d1);
    a1.z = __sinf(xy2.x * e1); a1.w = __cosf(xy2.y * e1);
    a2.x = __sinf(xy2.x * d2); a2.y = __cosf(xy2.y * d2);
    a2.z = __sinf(xy2.x * e2); a2.w = __cosf(xy2.y * e2);
    a3.x = __sinf(xy2.x * d3); a3.y = __cosf(xy2.y * d3);
    a3.z = __sinf(xy2.x * e3); a3.w = __cosf(xy2.y * e3);
    // row 1
    b0.x = __sinf(xy2.z * d0); b0.y = __cosf(xy2.w * d0);
    b0.z = __sinf(xy2.z * e0); b0.w = __cosf(xy2.w * e0);
    b1.x = __sinf(xy2.z * d1); b1.y = __cosf(xy2.w * d1);
    b1.z = __sinf(xy2.z * e1); b1.w = __cosf(xy2.w * e1);
    b2.x = __sinf(xy2.z * d2); b2.y = __cosf(xy2.w * d2);
    b2.z = __sinf(xy2.z * e2); b2.w = __cosf(xy2.w * e2);
    b3.x = __sinf(xy2.z * d3); b3.y = __cosf(xy2.w * d3);
    b3.z = __sinf(xy2.z * e3); b3.w = __cosf(xy2.w * e3);

    __stcs(o +   0, a0);
    __stcs(o +  32, a1);
    __stcs(o +  64, a2);
    __stcs(o +  96, a3);
    __stcs(o + 128, b0);
    __stcs(o + 160, b1);
    __stcs(o + 192, b2);
    __stcs(o + 224, b3);
}

extern "C" void kernel_launch(void* const* d_in, const int* in_sizes, int n_in,
                              void* d_out, int out_size) {
    const float4* x = (const float4*)d_in[0];
    float4* out = (float4*)d_out;
    // 65536 rows, 2 rows/warp, 8 warps/block -> 4096 blocks
    pe2d_kernel<<<NUM_ROWS / 16, 256>>>(x, out);
}

// round 6
// speedup vs baseline: 1.2506x; 1.2506x over previous
#include <cuda_runtime.h>
#include <cuda_bf16.h>

// PositionalEncoding2D:
//   pe[i, b, 2p]   = sin(x[i,b,0] * dt[p])
//   pe[i, b, 2p+1] = cos(x[i,b,1] * dt[p])
//   dt[p] = exp(p * -ln(1e4)/256)
//
// Input : x  [65536 rows][2] fp32;  Output: [65536 rows][512] fp32 = 128 MB.
// Store-bandwidth bound. One warp handles TWO rows; each lane produces 8
// float4 quads (4/row) -> 8 independent STG.128 in flight (MLP=8).
// PLAIN stores: R2 showed __stcs (.cs) takes a more expensive L1tex path on
// sm_103a (L1% up, DRAM% down, 45% slower) — reverted.
// (R3 run of this exact kernel died to container infra; resubmitting.)

#define NUM_ROWS (2048 * 32)   // 65536

__global__ __launch_bounds__(256)
void pe2d_kernel(const float4* __restrict__ x, float4* __restrict__ out) {
    const int warp = (blockIdx.x * 256 + threadIdx.x) >> 5;  // row-pair index
    const int lane = threadIdx.x & 31;

    // Coords for rows 2w and 2w+1: 4 contiguous floats (uniform in warp)
    const float4 xy2 = __ldg(x + warp);
    // row0: (xy2.x, xy2.y)   row1: (xy2.z, xy2.w)

    // dt for quad t: exp(2t * C), C = -ln(1e4)/256
    const float twoC = -9.210340371976184f / 128.0f;
    const float r    = 0.9646616199111993f;            // pair step 1e4^(-1/256)
    const float d0 = __expf((float)lane * twoC);       // quad lane
    const float d1 = d0 * 0.1f;                        // quad lane+32 (step = 1e4^(-1/4))
    const float d2 = d1 * 0.1f;
    const float d3 = d2 * 0.1f;
    const float e0 = d0 * r, e1 = d1 * r, e2 = d2 * r, e3 = d3 * r;

    float4* o = out + (size_t)warp * 256 + lane;

    float4 a;
    // row 0
    a.x = __sinf(xy2.x * d0); a.y = __cosf(xy2.y * d0);
    a.z = __sinf(xy2.x * e0); a.w = __cosf(xy2.y * e0);
    o[0] = a;
    a.x = __sinf(xy2.x * d1); a.y = __cosf(xy2.y * d1);
    a.z = __sinf(xy2.x * e1); a.w = __cosf(xy2.y * e1);
    o[32] = a;
    a.x = __sinf(xy2.x * d2); a.y = __cosf(xy2.y * d2);
    a.z = __sinf(xy2.x * e2); a.w = __cosf(xy2.y * e2);
    o[64] = a;
    a.x = __sinf(xy2.x * d3); a.y = __cosf(xy2.y * d3);
    a.z = __sinf(xy2.x * e3); a.w = __cosf(xy2.y * e3);
    o[96] = a;
    // row 1
    a.x = __sinf(xy2.z * d0); a.y = __cosf(xy2.w * d0);
    a.z = __sinf(xy2.z * e0); a.w = __cosf(xy2.w * e0);
    o[128] = a;
    a.x = __sinf(xy2.z * d1); a.y = __cosf(xy2.w * d1);
    a.z = __sinf(xy2.z * e1); a.w = __cosf(xy2.w * e1);
    o[160] = a;
    a.x = __sinf(xy2.z * d2); a.y = __cosf(xy2.w * d2);
    a.z = __sinf(xy2.z * e2); a.w = __cosf(xy2.w * e2);
    o[192] = a;
    a.x = __sinf(xy2.z * d3); a.y = __cosf(xy2.w * d3);
    a.z = __sinf(xy2.z * e3); a.w = __cosf(xy2.w * e3);
    o[224] = a;
}

extern "C" void kernel_launch(void* const* d_in, const int* in_sizes, int n_in,
                              void* d_out, int out_size) {
    const float4* x = (const float4*)d_in[0];
    float4* out = (float4*)d_out;
    // 65536 rows, 2 rows/warp, 8 warps/block -> 4096 blocks
    pe2d_kernel<<<NUM_ROWS / 16, 256>>>(x, out);
}